// round 3
// baseline (speedup 1.0000x reference)
#include <cuda_runtime.h>
#include <cuda_bf16.h>
#include <mma.h>

using namespace nvcuda;

// ---------------------------------------------------------------------------
// Problem constants
// ---------------------------------------------------------------------------
#define NBATCH 8192
#define SEQ    6
#define TOK    49152        // NBATCH * SEQ
#define DM     2048
#define NH     16
#define DH     128
#define LN_EPS 1e-5f

// ---------------------------------------------------------------------------
// Device-global scratch (the sanctioned workaround for no cudaMalloc)
// ---------------------------------------------------------------------------
__device__ __align__(256) float g_X[(size_t)TOK * DM];  // LN out, then attn out
__device__ __align__(256) float g_Q[(size_t)TOK * DM];
__device__ __align__(256) float g_K[(size_t)TOK * DM];
__device__ __align__(256) float g_V[(size_t)TOK * DM];

// ---------------------------------------------------------------------------
// cp.async helpers
// ---------------------------------------------------------------------------
__device__ __forceinline__ void cp_async16(void* smem_dst, const void* gmem_src) {
    unsigned s = (unsigned)__cvta_generic_to_shared(smem_dst);
    asm volatile("cp.async.ca.shared.global [%0], [%1], 16;\n" :: "r"(s), "l"(gmem_src));
}
__device__ __forceinline__ void cp_commit() {
    asm volatile("cp.async.commit_group;\n" ::: "memory");
}

// ---------------------------------------------------------------------------
// LayerNorm: one block (256 threads) per token, D = 2048
// ---------------------------------------------------------------------------
__global__ void __launch_bounds__(256) ln_kernel(
    const float* __restrict__ x, const float* __restrict__ gamma,
    const float* __restrict__ beta, float* __restrict__ out)
{
    int t   = blockIdx.x;
    int tid = threadIdx.x;
    const float4* xr = (const float4*)(x + (size_t)t * DM);

    float4 a = xr[tid];
    float4 b = xr[tid + 256];
    float s  = a.x + a.y + a.z + a.w + b.x + b.y + b.z + b.w;
    float ss = a.x*a.x + a.y*a.y + a.z*a.z + a.w*a.w
             + b.x*b.x + b.y*b.y + b.z*b.z + b.w*b.w;

    __shared__ float red[2][8];
    #pragma unroll
    for (int o = 16; o; o >>= 1) {
        s  += __shfl_xor_sync(0xffffffffu, s,  o);
        ss += __shfl_xor_sync(0xffffffffu, ss, o);
    }
    int wid = tid >> 5, lane = tid & 31;
    if (lane == 0) { red[0][wid] = s; red[1][wid] = ss; }
    __syncthreads();
    if (tid < 32) {
        float s2  = (tid < 8) ? red[0][tid] : 0.f;
        float ss2 = (tid < 8) ? red[1][tid] : 0.f;
        #pragma unroll
        for (int o = 4; o; o >>= 1) {
            s2  += __shfl_xor_sync(0xffffffffu, s2,  o);
            ss2 += __shfl_xor_sync(0xffffffffu, ss2, o);
        }
        if (tid == 0) { red[0][0] = s2; red[1][0] = ss2; }
    }
    __syncthreads();

    float mu  = red[0][0] * (1.f / DM);
    float var = red[1][0] * (1.f / DM) - mu * mu;
    float inv = rsqrtf(var + LN_EPS);

    const float4* g4 = (const float4*)gamma;
    const float4* b4 = (const float4*)beta;
    float4* o4 = (float4*)(out + (size_t)t * DM);

    float4 ga = g4[tid],       ba = b4[tid];
    float4 gb = g4[tid + 256], bb = b4[tid + 256];
    float4 r0, r1;
    r0.x = (a.x - mu) * inv * ga.x + ba.x;
    r0.y = (a.y - mu) * inv * ga.y + ba.y;
    r0.z = (a.z - mu) * inv * ga.z + ba.z;
    r0.w = (a.w - mu) * inv * ga.w + ba.w;
    r1.x = (b.x - mu) * inv * gb.x + bb.x;
    r1.y = (b.y - mu) * inv * gb.y + bb.y;
    r1.z = (b.z - mu) * inv * gb.z + bb.z;
    r1.w = (b.w - mu) * inv * gb.w + bb.w;
    o4[tid]       = r0;
    o4[tid + 256] = r1;
}

// ---------------------------------------------------------------------------
// tf32 GEMM:  C[M=49152, N=2048] = A[M,2048] @ W[N=2048, K=2048]^T + bias (+ resid)
// Tiles: BM=128, BN=128, BK=16; 2-stage cp.async; 8 warps, warp tile 32x64.
// Grid: (N/128 = 16, M/128 = 384). All dims divide evenly -> no predicates.
// ---------------------------------------------------------------------------
#define BK   16
#define KPAD 20   // 16 + 4 pad floats; row stride = 80B (16B multiple)
#define NK   (DM / BK)   // 128 k-tiles

__global__ void __launch_bounds__(256) gemm_kernel(
    const float* __restrict__ A, const float* __restrict__ W,
    const float* __restrict__ bias, const float* __restrict__ resid,
    float* __restrict__ C)
{
    __shared__ __align__(16) float sA[2][128 * KPAD];
    __shared__ __align__(16) float sB[2][128 * KPAD];

    int tid = threadIdx.x;
    int n0  = blockIdx.x * 128;
    int m0  = blockIdx.y * 128;
    const float* Ab = A + (size_t)m0 * DM;
    const float* Wb = W + (size_t)n0 * DM;

    wmma::fragment<wmma::accumulator, 16, 16, 8, float> acc[2][4];
    #pragma unroll
    for (int i = 0; i < 2; i++)
        #pragma unroll
        for (int j = 0; j < 4; j++)
            wmma::fill_fragment(acc[i][j], 0.f);

    int wid = tid >> 5;
    int wm  = wid & 3;       // 4 warps along M
    int wn  = wid >> 2;      // 2 warps along N
    int lane = tid & 31;

    // stage loader: 512 float4 per (A|B) tile half -> 2 per thread each
    auto load_stage = [&](int buf, int kt) {
        int k0 = kt * BK;
        #pragma unroll
        for (int u = 0; u < 2; u++) {
            int idx = tid + u * 256;       // 0..511
            int row = idx >> 2;            // 0..127
            int c4  = (idx & 3) * 4;       // 0,4,8,12
            cp_async16(&sA[buf][row * KPAD + c4], Ab + (size_t)row * DM + k0 + c4);
            cp_async16(&sB[buf][row * KPAD + c4], Wb + (size_t)row * DM + k0 + c4);
        }
        cp_commit();
    };

    load_stage(0, 0);

    for (int kt = 0; kt < NK; kt++) {
        if (kt + 1 < NK) {
            load_stage((kt + 1) & 1, kt + 1);
            asm volatile("cp.async.wait_group 1;\n" ::: "memory");
        } else {
            asm volatile("cp.async.wait_group 0;\n" ::: "memory");
        }
        __syncthreads();

        const float* ap = &sA[kt & 1][0];
        const float* bp = &sB[kt & 1][0];
        #pragma unroll
        for (int kk = 0; kk < BK; kk += 8) {
            wmma::fragment<wmma::matrix_a, 16, 16, 8, wmma::precision::tf32, wmma::row_major> af[2];
            wmma::fragment<wmma::matrix_b, 16, 16, 8, wmma::precision::tf32, wmma::col_major> bf[4];
            #pragma unroll
            for (int i = 0; i < 2; i++) {
                wmma::load_matrix_sync(af[i], ap + (wm * 32 + i * 16) * KPAD + kk, KPAD);
                #pragma unroll
                for (int t = 0; t < af[i].num_elements; t++)
                    af[i].x[t] = wmma::__float_to_tf32(af[i].x[t]);
            }
            #pragma unroll
            for (int j = 0; j < 4; j++) {
                wmma::load_matrix_sync(bf[j], bp + (wn * 64 + j * 16) * KPAD + kk, KPAD);
                #pragma unroll
                for (int t = 0; t < bf[j].num_elements; t++)
                    bf[j].x[t] = wmma::__float_to_tf32(bf[j].x[t]);
            }
            #pragma unroll
            for (int i = 0; i < 2; i++)
                #pragma unroll
                for (int j = 0; j < 4; j++)
                    wmma::mma_sync(acc[i][j], af[i], bf[j], acc[i][j]);
        }
        __syncthreads();
    }

    // epilogue: per-warp 16x16 frag -> smem -> global (+bias, +resid)
    float* epi = &sA[0][wid * 320];   // 16 rows x ld 20 = 320 floats per warp
    #pragma unroll
    for (int i = 0; i < 2; i++) {
        #pragma unroll
        for (int j = 0; j < 4; j++) {
            wmma::store_matrix_sync(epi, acc[i][j], KPAD, wmma::mem_row_major);
            __syncwarp();
            int grow0 = m0 + wm * 32 + i * 16;
            int gcol0 = n0 + wn * 64 + j * 16;
            #pragma unroll
            for (int e = 0; e < 8; e++) {
                int idx = e * 32 + lane;
                int r = idx >> 4, c = idx & 15;
                size_t off = (size_t)(grow0 + r) * DM + gcol0 + c;
                float v = epi[r * KPAD + c] + bias[gcol0 + c];
                if (resid) v += resid[off];
                C[off] = v;
            }
            __syncwarp();
        }
    }
}

// ---------------------------------------------------------------------------
// Attention: one warp per (batch, head). S=6, DH=128; lane owns 4 head dims.
// scores = (Q K^T / sqrt(DH)) * sigmoid(routing); softmax over k; out = attn V
// Q/K/V/out are token-major [TOK, DM] with head h at columns [h*128, h*128+128)
// ---------------------------------------------------------------------------
__global__ void __launch_bounds__(128) attn_kernel(
    const float* __restrict__ Q, const float* __restrict__ K,
    const float* __restrict__ V, const float* __restrict__ routing,
    float* __restrict__ O)
{
    int wg   = blockIdx.x * 4 + (threadIdx.x >> 5);  // b*NH + h
    int lane = threadIdx.x & 31;
    int b = wg >> 4, h = wg & 15;
    size_t base = (size_t)b * SEQ * DM + (size_t)h * DH + lane * 4;

    float4 q[SEQ], k[SEQ], v[SEQ];
    #pragma unroll
    for (int s = 0; s < SEQ; s++) {
        q[s] = *(const float4*)(Q + base + (size_t)s * DM);
        k[s] = *(const float4*)(K + base + (size_t)s * DM);
        v[s] = *(const float4*)(V + base + (size_t)s * DM);
    }

    float sc[SEQ * SEQ];
    #pragma unroll
    for (int i = 0; i < SEQ; i++)
        #pragma unroll
        for (int j = 0; j < SEQ; j++)
            sc[i * SEQ + j] = q[i].x * k[j].x + q[i].y * k[j].y
                            + q[i].z * k[j].z + q[i].w * k[j].w;

    #pragma unroll
    for (int t = 0; t < SEQ * SEQ; t++)
        #pragma unroll
        for (int o = 16; o; o >>= 1)
            sc[t] += __shfl_xor_sync(0xffffffffu, sc[t], o);

    const float scale = 0.08838834764831845f;  // 1/sqrt(128)
    #pragma unroll
    for (int i = 0; i < SEQ; i++)
        #pragma unroll
        for (int j = 0; j < SEQ; j++) {
            float r = routing[i * SEQ + j];
            float m = 1.f / (1.f + expf(-r));
            sc[i * SEQ + j] *= scale * m;
        }

    #pragma unroll
    for (int i = 0; i < SEQ; i++) {
        float mx = sc[i * SEQ];
        #pragma unroll
        for (int j = 1; j < SEQ; j++) mx = fmaxf(mx, sc[i * SEQ + j]);
        float sum = 0.f;
        #pragma unroll
        for (int j = 0; j < SEQ; j++) {
            sc[i * SEQ + j] = expf(sc[i * SEQ + j] - mx);
            sum += sc[i * SEQ + j];
        }
        float rs = 1.f / sum;
        #pragma unroll
        for (int j = 0; j < SEQ; j++) sc[i * SEQ + j] *= rs;
    }

    #pragma unroll
    for (int i = 0; i < SEQ; i++) {
        float4 o = make_float4(0.f, 0.f, 0.f, 0.f);
        #pragma unroll
        for (int j = 0; j < SEQ; j++) {
            float p = sc[i * SEQ + j];
            o.x += p * v[j].x; o.y += p * v[j].y;
            o.z += p * v[j].z; o.w += p * v[j].w;
        }
        *(float4*)(O + base + (size_t)i * DM) = o;
    }
}

// ---------------------------------------------------------------------------
// kernel_launch
// inputs: 0 stream_embeddings, 1 Wq, 2 bq, 3 Wk, 4 bk, 5 Wv, 6 bv,
//         7 Wo, 8 bo, 9 routing_logits, 10 gamma, 11 beta
// ---------------------------------------------------------------------------
extern "C" void kernel_launch(void* const* d_in, const int* in_sizes, int n_in,
                              void* d_out, int out_size)
{
    (void)in_sizes; (void)n_in; (void)out_size;
    const float* x       = (const float*)d_in[0];
    const float* Wq      = (const float*)d_in[1];
    const float* bq      = (const float*)d_in[2];
    const float* Wk      = (const float*)d_in[3];
    const float* bk      = (const float*)d_in[4];
    const float* Wv      = (const float*)d_in[5];
    const float* bv      = (const float*)d_in[6];
    const float* Wo      = (const float*)d_in[7];
    const float* bo      = (const float*)d_in[8];
    const float* routing = (const float*)d_in[9];
    const float* gamma   = (const float*)d_in[10];
    const float* beta    = (const float*)d_in[11];
    float* out = (float*)d_out;

    float *X, *Qb, *Kb, *Vb;
    cudaGetSymbolAddress((void**)&X,  g_X);
    cudaGetSymbolAddress((void**)&Qb, g_Q);
    cudaGetSymbolAddress((void**)&Kb, g_K);
    cudaGetSymbolAddress((void**)&Vb, g_V);

    ln_kernel<<<TOK, 256>>>(x, gamma, beta, X);

    dim3 gg(DM / 128, TOK / 128);   // (16, 384)
    gemm_kernel<<<gg, 256>>>(X, Wq, bq, nullptr, Qb);
    gemm_kernel<<<gg, 256>>>(X, Wk, bk, nullptr, Kb);
    gemm_kernel<<<gg, 256>>>(X, Wv, bv, nullptr, Vb);

    attn_kernel<<<(NBATCH * NH) / 4, 128>>>(Qb, Kb, Vb, routing, X);

    gemm_kernel<<<gg, 256>>>(X, Wo, bo, x /*residual*/, out);
}